// round 9
// baseline (speedup 1.0000x reference)
#include <cuda_runtime.h>

#define B_N   1024
#define C_N   128
#define I_N   16
#define E_N   10
#define NT3   816           // cubic monomials i0<=i1<=i2
#define NT2   136           // quadratic monomials
#define NT    968           // 816 + 136 + 16
#define NCOMP 4             // L=0 scalar + 3 components of L=1

typedef unsigned long long u64;

// ---------------- device scratch (static globals; no allocation) ----------------
__device__ int   g_perm[B_N];
__device__ int   g_segstart[E_N + 1];
__device__ __align__(32) float g_U3S[NCOMP][NT3][8];
__device__ __align__(16) float g_U2S[NCOMP][NT2][4];
__device__ float g_U1S[NCOMP][I_N];
// duplicated coefficient table: [e][c][t] -> {c0,c0,c1,c1},{c2,c2,c3,c3}
__device__ __align__(16) float g_coef2[E_N * C_N * NT * 8];  // 39.7 MB

// ---------------- packed f32x2 helpers (pack = {item0, item1}) ------------------
__device__ __forceinline__ u64 packpair(float lo, float hi) {
    u64 r;
    asm("mov.b64 %0, {%1, %2};" : "=l"(r) : "f"(lo), "f"(hi));
    return r;
}
__device__ __forceinline__ u64 fma2(u64 a, u64 b, u64 c) {
    u64 d;
    asm("fma.rn.f32x2 %0, %1, %2, %3;" : "=l"(d) : "l"(a), "l"(b), "l"(c));
    return d;
}
__device__ __forceinline__ void unpackpair(u64 v, float& lo, float& hi) {
    asm("mov.b64 {%0, %1}, %2;" : "=f"(lo), "=f"(hi) : "l"(v));
}

// ---------------- kernel A: sort (block 0) + U symmetrization (blocks 1..32) ---
__global__ void prep_kernel(const float* __restrict__ node_attrs,
                            const float* __restrict__ U3_l0,
                            const float* __restrict__ U3_l1,
                            const float* __restrict__ U2_l0,
                            const float* __restrict__ U2_l1,
                            const float* __restrict__ U1_l0,
                            const float* __restrict__ U1_l1) {
    int tid = threadIdx.x;   // 1024
    if (blockIdx.x == 0) {
        __shared__ int s_hist[E_N];
        __shared__ int s_off[E_N];
        if (tid < E_N) s_hist[tid] = 0;
        __syncthreads();
        const float* na = node_attrs + tid * E_N;
        int e = 0;
#pragma unroll
        for (int j = 0; j < E_N; j++) if (na[j] > 0.5f) e = j;
        atomicAdd(&s_hist[e], 1);
        __syncthreads();
        if (tid == 0) {
            int acc = 0;
            for (int j = 0; j < E_N; j++) {
                s_off[j] = acc; g_segstart[j] = acc; acc += s_hist[j];
            }
            g_segstart[E_N] = acc;
        }
        __syncthreads();
        int pos = atomicAdd(&s_off[e], 1);
        g_perm[pos] = tid;
        return;
    }

    int gtid = (blockIdx.x - 1) * blockDim.x + tid;   // 0..32767

    if (gtid < NCOMP * NT3 * 8) {
        int k    = gtid & 7;
        int t    = (gtid >> 3) % NT3;
        int comp = gtid / (NT3 * 8);
        int rem = t, a = 0;
        for (int ap = 0; ap < I_N; ap++) {
            int sz = (I_N - ap) * (I_N - ap + 1) / 2;
            if (rem < sz) { a = ap; break; }
            rem -= sz;
        }
        int b = a;
        for (int bp = a; bp < I_N; bp++) {
            int sz = I_N - bp;
            if (rem < sz) { b = bp; break; }
            rem -= sz;
        }
        int c = b + rem;
        float inv = (a == c) ? (1.f / 6.f) : ((a == b || b == c) ? 0.5f : 1.f);
        int kN; const float* U;
        if (comp == 0) { kN = 5; U = U3_l0; }
        else           { kN = 7; U = U3_l1 + (comp - 1) * (I_N * I_N * I_N * 7); }
        float s = 0.f;
        if (k < kN) {
            auto at = [&](int i0, int i1, int i2) {
                return U[((i0 * I_N + i1) * I_N + i2) * kN + k];
            };
            s = at(a,b,c) + at(a,c,b) + at(b,a,c) + at(b,c,a) + at(c,a,b) + at(c,b,a);
            s *= inv;
        }
        g_U3S[comp][t][k] = s;
    }
    if (gtid < NCOMP * NT2 * 4) {
        int k    = gtid & 3;
        int t    = (gtid >> 2) % NT2;
        int comp = gtid / (NT2 * 4);
        int rem = t, a = 0;
        for (int ap = 0; ap < I_N; ap++) {
            int sz = I_N - ap;
            if (rem < sz) { a = ap; break; }
            rem -= sz;
        }
        int b = a + rem;
        int kN; const float* U;
        if (comp == 0) { kN = 2; U = U2_l0; }
        else           { kN = 3; U = U2_l1 + (comp - 1) * (I_N * I_N * 3); }
        float s = 0.f;
        if (k < kN) {
            s = U[(a * I_N + b) * kN + k];
            if (a != b) s += U[(b * I_N + a) * kN + k];
        }
        g_U2S[comp][t][k] = s;
    }
    if (gtid < NCOMP * I_N) {
        int comp = gtid / I_N, i = gtid % I_N;
        g_U1S[comp][i] = (comp == 0) ? U1_l0[i] : U1_l1[(comp - 1) * I_N + i];
    }
}

// ---------------- kernel B: coefficient fold, duplicated-pair output ------------
__global__ void __launch_bounds__(256) coef_kernel(const float* __restrict__ W3_l0,
                                                   const float* __restrict__ W2_l0,
                                                   const float* __restrict__ W1_l0,
                                                   const float* __restrict__ W3_l1,
                                                   const float* __restrict__ W2_l1,
                                                   const float* __restrict__ W1_l1) {
    int c   = blockIdx.x;
    int tid = threadIdx.x;   // 256
    __shared__ float sw30[E_N][5], sw31[E_N][7];
    __shared__ float sw20[E_N][2], sw21[E_N][3];
    __shared__ float sw10[E_N], sw11[E_N];
    if (tid < E_N * 5) sw30[tid / 5][tid % 5] = W3_l0[tid * C_N + c];
    if (tid < E_N * 7) sw31[tid / 7][tid % 7] = W3_l1[tid * C_N + c];
    if (tid < E_N * 2) sw20[tid / 2][tid % 2] = W2_l0[tid * C_N + c];
    if (tid < E_N * 3) sw21[tid / 3][tid % 3] = W2_l1[tid * C_N + c];
    if (tid < E_N) { sw10[tid] = W1_l0[tid * C_N + c]; sw11[tid] = W1_l1[tid * C_N + c]; }
    __syncthreads();

    float4* dst = reinterpret_cast<float4*>(g_coef2);

    for (int t = tid; t < NT3; t += 256) {
        float4 A0 = reinterpret_cast<const float4*>(&g_U3S[0][t][0])[0];
        float4 A1 = reinterpret_cast<const float4*>(&g_U3S[0][t][0])[1];
        float4 B0 = reinterpret_cast<const float4*>(&g_U3S[1][t][0])[0];
        float4 B1 = reinterpret_cast<const float4*>(&g_U3S[1][t][0])[1];
        float4 C0 = reinterpret_cast<const float4*>(&g_U3S[2][t][0])[0];
        float4 C1 = reinterpret_cast<const float4*>(&g_U3S[2][t][0])[1];
        float4 D0 = reinterpret_cast<const float4*>(&g_U3S[3][t][0])[0];
        float4 D1 = reinterpret_cast<const float4*>(&g_U3S[3][t][0])[1];
#pragma unroll
        for (int e = 0; e < E_N; e++) {
            float c0 = A0.x*sw30[e][0] + A0.y*sw30[e][1] + A0.z*sw30[e][2]
                     + A0.w*sw30[e][3] + A1.x*sw30[e][4];
            float c1 = B0.x*sw31[e][0] + B0.y*sw31[e][1] + B0.z*sw31[e][2]
                     + B0.w*sw31[e][3] + B1.x*sw31[e][4] + B1.y*sw31[e][5] + B1.z*sw31[e][6];
            float c2 = C0.x*sw31[e][0] + C0.y*sw31[e][1] + C0.z*sw31[e][2]
                     + C0.w*sw31[e][3] + C1.x*sw31[e][4] + C1.y*sw31[e][5] + C1.z*sw31[e][6];
            float c3 = D0.x*sw31[e][0] + D0.y*sw31[e][1] + D0.z*sw31[e][2]
                     + D0.w*sw31[e][3] + D1.x*sw31[e][4] + D1.y*sw31[e][5] + D1.z*sw31[e][6];
            int base = ((e * C_N + c) * NT + t) * 2;
            dst[base]     = make_float4(c0, c0, c1, c1);
            dst[base + 1] = make_float4(c2, c2, c3, c3);
        }
    }
    for (int t = tid; t < NT2; t += 256) {
        float4 Q0 = reinterpret_cast<const float4*>(&g_U2S[0][t][0])[0];
        float4 Q1 = reinterpret_cast<const float4*>(&g_U2S[1][t][0])[0];
        float4 Q2 = reinterpret_cast<const float4*>(&g_U2S[2][t][0])[0];
        float4 Q3 = reinterpret_cast<const float4*>(&g_U2S[3][t][0])[0];
#pragma unroll
        for (int e = 0; e < E_N; e++) {
            float c0 = Q0.x*sw20[e][0] + Q0.y*sw20[e][1];
            float c1 = Q1.x*sw21[e][0] + Q1.y*sw21[e][1] + Q1.z*sw21[e][2];
            float c2 = Q2.x*sw21[e][0] + Q2.y*sw21[e][1] + Q2.z*sw21[e][2];
            float c3 = Q3.x*sw21[e][0] + Q3.y*sw21[e][1] + Q3.z*sw21[e][2];
            int base = ((e * C_N + c) * NT + NT3 + t) * 2;
            dst[base]     = make_float4(c0, c0, c1, c1);
            dst[base + 1] = make_float4(c2, c2, c3, c3);
        }
    }
    if (tid < I_N) {
        int i = tid;
#pragma unroll
        for (int e = 0; e < E_N; e++) {
            float c0 = g_U1S[0][i] * sw10[e];
            float c1 = g_U1S[1][i] * sw11[e];
            float c2 = g_U1S[2][i] * sw11[e];
            float c3 = g_U1S[3][i] * sw11[e];
            int base = ((e * C_N + c) * NT + NT3 + NT2 + i) * 2;
            dst[base]     = make_float4(c0, c0, c1, c1);
            dst[base + 1] = make_float4(c2, c2, c3, c3);
        }
    }
}

// ---------------- kernel C: evaluation, Horner + f32x2 item-packing -------------
// block = (channel c, species e), 64 threads, 2 items/thread packed into the
// two lanes of f32x2: halves fma-pipe instruction count vs scalar FFMA.
// Coefficients stored duplicated {c,c} so they are direct f32x2 operands.
__global__ void __launch_bounds__(64, 7) main_kernel(const float* __restrict__ a_i,
                                                     float* __restrict__ out) {
    __shared__ __align__(16) ulonglong2 s_coef[NT * 2];  // 31 KB: [t*2]={c0c0,c1c1}
    int c   = blockIdx.x;
    int e   = blockIdx.y;
    int tid = threadIdx.x;

    const float4* src = reinterpret_cast<const float4*>(
        g_coef2 + (e * C_N + c) * NT * 8);
#pragma unroll 4
    for (int i = tid; i < NT * 2; i += 64)
        reinterpret_cast<float4*>(s_coef)[i] = src[i];
    __syncthreads();

    int start = g_segstart[e], end = g_segstart[e + 1];

    for (int p0 = start + tid; p0 < end; p0 += 128) {
        int  p1   = p0 + 64;
        bool has1 = (p1 < end);
        int  b0   = g_perm[p0];
        int  b1   = g_perm[has1 ? p1 : p0];

        u64 xx[16];
        {
            const float4* xq = reinterpret_cast<const float4*>(a_i + (b0 * C_N + c) * I_N);
            const float4* xr = reinterpret_cast<const float4*>(a_i + (b1 * C_N + c) * I_N);
            float4 q0 = xq[0], q1 = xq[1], q2 = xq[2], q3 = xq[3];
            float4 r0 = xr[0], r1 = xr[1], r2 = xr[2], r3 = xr[3];
            xx[0]  = packpair(q0.x, r0.x);  xx[1]  = packpair(q0.y, r0.y);
            xx[2]  = packpair(q0.z, r0.z);  xx[3]  = packpair(q0.w, r0.w);
            xx[4]  = packpair(q1.x, r1.x);  xx[5]  = packpair(q1.y, r1.y);
            xx[6]  = packpair(q1.z, r1.z);  xx[7]  = packpair(q1.w, r1.w);
            xx[8]  = packpair(q2.x, r2.x);  xx[9]  = packpair(q2.y, r2.y);
            xx[10] = packpair(q2.z, r2.z);  xx[11] = packpair(q2.w, r2.w);
            xx[12] = packpair(q3.x, r3.x);  xx[13] = packpair(q3.y, r3.y);
            xx[14] = packpair(q3.z, r3.z);  xx[15] = packpair(q3.w, r3.w);
        }

        u64 o0 = 0ull, o1 = 0ull, o2 = 0ull, o3 = 0ull;  // {0.f,0.f}
        int t = 0, tp = 0;
#pragma unroll
        for (int a = 0; a < I_N; a++) {
            u64 t20, t21, t22, t23;
            ulonglong2 clA = s_coef[(NT3 + NT2 + a) * 2];
            ulonglong2 clB = s_coef[(NT3 + NT2 + a) * 2 + 1];
#pragma unroll
            for (int b2 = a; b2 < I_N; b2++) {
                ulonglong2 cqA = s_coef[(NT3 + tp) * 2];
                ulonglong2 cqB = s_coef[(NT3 + tp) * 2 + 1];
                tp++;
                u64 t30, t31, t32, t33;
                {   // c3 == b2 term absorbs the quadratic coefficient
                    ulonglong2 cfA = s_coef[t * 2];
                    ulonglong2 cfB = s_coef[t * 2 + 1];
                    t++;
                    t30 = fma2(cfA.x, xx[b2], cqA.x);
                    t31 = fma2(cfA.y, xx[b2], cqA.y);
                    t32 = fma2(cfB.x, xx[b2], cqB.x);
                    t33 = fma2(cfB.y, xx[b2], cqB.y);
                }
#pragma unroll
                for (int c3 = b2 + 1; c3 < I_N; c3++) {
                    ulonglong2 cfA = s_coef[t * 2];
                    ulonglong2 cfB = s_coef[t * 2 + 1];
                    t++;
                    t30 = fma2(cfA.x, xx[c3], t30);
                    t31 = fma2(cfA.y, xx[c3], t31);
                    t32 = fma2(cfB.x, xx[c3], t32);
                    t33 = fma2(cfB.y, xx[c3], t33);
                }
                if (b2 == a) {   // first b-fold absorbs the linear coefficient
                    t20 = fma2(t30, xx[b2], clA.x);
                    t21 = fma2(t31, xx[b2], clA.y);
                    t22 = fma2(t32, xx[b2], clB.x);
                    t23 = fma2(t33, xx[b2], clB.y);
                } else {
                    t20 = fma2(t30, xx[b2], t20);
                    t21 = fma2(t31, xx[b2], t21);
                    t22 = fma2(t32, xx[b2], t22);
                    t23 = fma2(t33, xx[b2], t23);
                }
            }
            o0 = fma2(t20, xx[a], o0);
            o1 = fma2(t21, xx[a], o1);
            o2 = fma2(t22, xx[a], o2);
            o3 = fma2(t23, xx[a], o3);
        }

        float a00, a10, a01, a11, a02, a12, a03, a13;
        unpackpair(o0, a00, a10);
        unpackpair(o1, a01, a11);
        unpackpair(o2, a02, a12);
        unpackpair(o3, a03, a13);

        // output layout: [b, 512] = concat(out0[b, c], out1[b, c*3+m])
        {
            float* ob = out + b0 * 512;
            ob[c]               = a00;
            ob[128 + c * 3 + 0] = a01;
            ob[128 + c * 3 + 1] = a02;
            ob[128 + c * 3 + 2] = a03;
        }
        if (has1) {
            float* ob = out + b1 * 512;
            ob[c]               = a10;
            ob[128 + c * 3 + 0] = a11;
            ob[128 + c * 3 + 1] = a12;
            ob[128 + c * 3 + 2] = a13;
        }
    }
}

// ---------------- launch --------------------------------------------------------
extern "C" void kernel_launch(void* const* d_in, const int* in_sizes, int n_in,
                              void* d_out, int out_size) {
    const float* a_i   = (const float*)d_in[0];
    const float* na    = (const float*)d_in[1];
    const float* U3_l0 = (const float*)d_in[2];
    const float* U2_l0 = (const float*)d_in[3];
    const float* U1_l0 = (const float*)d_in[4];
    const float* W3_l0 = (const float*)d_in[5];
    const float* W2_l0 = (const float*)d_in[6];
    const float* W1_l0 = (const float*)d_in[7];
    const float* U3_l1 = (const float*)d_in[8];
    const float* U2_l1 = (const float*)d_in[9];
    const float* U1_l1 = (const float*)d_in[10];
    const float* W3_l1 = (const float*)d_in[11];
    const float* W2_l1 = (const float*)d_in[12];
    const float* W1_l1 = (const float*)d_in[13];
    float* out = (float*)d_out;

    prep_kernel<<<33, 1024>>>(na, U3_l0, U3_l1, U2_l0, U2_l1, U1_l0, U1_l1);
    coef_kernel<<<C_N, 256>>>(W3_l0, W2_l0, W1_l0, W3_l1, W2_l1, W1_l1);
    dim3 grid(C_N, E_N);
    main_kernel<<<grid, 64>>>(a_i, out);
}

// round 10
// speedup vs baseline: 5.6780x; 5.6780x over previous
#include <cuda_runtime.h>

#define B_N   1024
#define C_N   128
#define I_N   16
#define E_N   10
#define NT3   816           // cubic monomials i0<=i1<=i2
#define NT2   136           // quadratic monomials
#define NT    968           // 816 + 136 + 16
#define NCOMP 4             // L=0 scalar + 3 components of L=1

// ---------------- device scratch (static globals; no allocation) ----------------
__device__ int   g_perm[B_N];
__device__ int   g_segstart[E_N + 1];
__device__ __align__(32) float g_U3S[NCOMP][NT3][8];
__device__ __align__(16) float g_U2S[NCOMP][NT2][4];
__device__ float g_U1S[NCOMP][I_N];
// coefficient table: [e][c][t][comp] -> per-(e,c) slab contiguous 15.5 KB
__device__ __align__(16) float g_coef[E_N * C_N * NT * NCOMP];  // 19.8 MB

// ---------------- kernel A: sort (block 0) + U symmetrization (blocks 1..32) ---
__global__ void prep_kernel(const float* __restrict__ node_attrs,
                            const float* __restrict__ U3_l0,
                            const float* __restrict__ U3_l1,
                            const float* __restrict__ U2_l0,
                            const float* __restrict__ U2_l1,
                            const float* __restrict__ U1_l0,
                            const float* __restrict__ U1_l1) {
    int tid = threadIdx.x;   // 1024
    if (blockIdx.x == 0) {
        __shared__ int s_hist[E_N];
        __shared__ int s_off[E_N];
        if (tid < E_N) s_hist[tid] = 0;
        __syncthreads();
        const float* na = node_attrs + tid * E_N;
        int e = 0;
#pragma unroll
        for (int j = 0; j < E_N; j++) if (na[j] > 0.5f) e = j;
        atomicAdd(&s_hist[e], 1);
        __syncthreads();
        if (tid == 0) {
            int acc = 0;
            for (int j = 0; j < E_N; j++) {
                s_off[j] = acc; g_segstart[j] = acc; acc += s_hist[j];
            }
            g_segstart[E_N] = acc;
        }
        __syncthreads();
        int pos = atomicAdd(&s_off[e], 1);
        g_perm[pos] = tid;
        return;
    }

    int gtid = (blockIdx.x - 1) * blockDim.x + tid;   // 0..32767

    if (gtid < NCOMP * NT3 * 8) {
        int k    = gtid & 7;
        int t    = (gtid >> 3) % NT3;
        int comp = gtid / (NT3 * 8);
        int rem = t, a = 0;
        for (int ap = 0; ap < I_N; ap++) {
            int sz = (I_N - ap) * (I_N - ap + 1) / 2;
            if (rem < sz) { a = ap; break; }
            rem -= sz;
        }
        int b = a;
        for (int bp = a; bp < I_N; bp++) {
            int sz = I_N - bp;
            if (rem < sz) { b = bp; break; }
            rem -= sz;
        }
        int c = b + rem;
        float inv = (a == c) ? (1.f / 6.f) : ((a == b || b == c) ? 0.5f : 1.f);
        int kN; const float* U;
        if (comp == 0) { kN = 5; U = U3_l0; }
        else           { kN = 7; U = U3_l1 + (comp - 1) * (I_N * I_N * I_N * 7); }
        float s = 0.f;
        if (k < kN) {
            auto at = [&](int i0, int i1, int i2) {
                return U[((i0 * I_N + i1) * I_N + i2) * kN + k];
            };
            s = at(a,b,c) + at(a,c,b) + at(b,a,c) + at(b,c,a) + at(c,a,b) + at(c,b,a);
            s *= inv;
        }
        g_U3S[comp][t][k] = s;
    }
    if (gtid < NCOMP * NT2 * 4) {
        int k    = gtid & 3;
        int t    = (gtid >> 2) % NT2;
        int comp = gtid / (NT2 * 4);
        int rem = t, a = 0;
        for (int ap = 0; ap < I_N; ap++) {
            int sz = I_N - ap;
            if (rem < sz) { a = ap; break; }
            rem -= sz;
        }
        int b = a + rem;
        int kN; const float* U;
        if (comp == 0) { kN = 2; U = U2_l0; }
        else           { kN = 3; U = U2_l1 + (comp - 1) * (I_N * I_N * 3); }
        float s = 0.f;
        if (k < kN) {
            s = U[(a * I_N + b) * kN + k];
            if (a != b) s += U[(b * I_N + a) * kN + k];
        }
        g_U2S[comp][t][k] = s;
    }
    if (gtid < NCOMP * I_N) {
        int comp = gtid / I_N, i = gtid % I_N;
        g_U1S[comp][i] = (comp == 0) ? U1_l0[i] : U1_l1[(comp - 1) * I_N + i];
    }
}

// ---------------- kernel B: coefficient fold, one block per channel -------------
__global__ void __launch_bounds__(512) coef_kernel(const float* __restrict__ W3_l0,
                                                   const float* __restrict__ W2_l0,
                                                   const float* __restrict__ W1_l0,
                                                   const float* __restrict__ W3_l1,
                                                   const float* __restrict__ W2_l1,
                                                   const float* __restrict__ W1_l1) {
    int c   = blockIdx.x;
    int tid = threadIdx.x;   // 512
    __shared__ float sw30[E_N][5], sw31[E_N][7];
    __shared__ float sw20[E_N][2], sw21[E_N][3];
    __shared__ float sw10[E_N], sw11[E_N];
    if (tid < E_N * 5) sw30[tid / 5][tid % 5] = W3_l0[tid * C_N + c];
    if (tid < E_N * 7) sw31[tid / 7][tid % 7] = W3_l1[tid * C_N + c];
    if (tid < E_N * 2) sw20[tid / 2][tid % 2] = W2_l0[tid * C_N + c];
    if (tid < E_N * 3) sw21[tid / 3][tid % 3] = W2_l1[tid * C_N + c];
    if (tid < E_N) { sw10[tid] = W1_l0[tid * C_N + c]; sw11[tid] = W1_l1[tid * C_N + c]; }
    __syncthreads();

    for (int t = tid; t < NT3; t += 512) {
        float4 A0 = reinterpret_cast<const float4*>(&g_U3S[0][t][0])[0];
        float4 A1 = reinterpret_cast<const float4*>(&g_U3S[0][t][0])[1];
        float4 B0 = reinterpret_cast<const float4*>(&g_U3S[1][t][0])[0];
        float4 B1 = reinterpret_cast<const float4*>(&g_U3S[1][t][0])[1];
        float4 C0 = reinterpret_cast<const float4*>(&g_U3S[2][t][0])[0];
        float4 C1 = reinterpret_cast<const float4*>(&g_U3S[2][t][0])[1];
        float4 D0 = reinterpret_cast<const float4*>(&g_U3S[3][t][0])[0];
        float4 D1 = reinterpret_cast<const float4*>(&g_U3S[3][t][0])[1];
#pragma unroll
        for (int e = 0; e < E_N; e++) {
            float c0 = A0.x*sw30[e][0] + A0.y*sw30[e][1] + A0.z*sw30[e][2]
                     + A0.w*sw30[e][3] + A1.x*sw30[e][4];
            float c1 = B0.x*sw31[e][0] + B0.y*sw31[e][1] + B0.z*sw31[e][2]
                     + B0.w*sw31[e][3] + B1.x*sw31[e][4] + B1.y*sw31[e][5] + B1.z*sw31[e][6];
            float c2 = C0.x*sw31[e][0] + C0.y*sw31[e][1] + C0.z*sw31[e][2]
                     + C0.w*sw31[e][3] + C1.x*sw31[e][4] + C1.y*sw31[e][5] + C1.z*sw31[e][6];
            float c3 = D0.x*sw31[e][0] + D0.y*sw31[e][1] + D0.z*sw31[e][2]
                     + D0.w*sw31[e][3] + D1.x*sw31[e][4] + D1.y*sw31[e][5] + D1.z*sw31[e][6];
            reinterpret_cast<float4*>(g_coef)[(e * C_N + c) * NT + t] =
                make_float4(c0, c1, c2, c3);
        }
    }
    for (int t = tid; t < NT2; t += 512) {
        float4 Q0 = reinterpret_cast<const float4*>(&g_U2S[0][t][0])[0];
        float4 Q1 = reinterpret_cast<const float4*>(&g_U2S[1][t][0])[0];
        float4 Q2 = reinterpret_cast<const float4*>(&g_U2S[2][t][0])[0];
        float4 Q3 = reinterpret_cast<const float4*>(&g_U2S[3][t][0])[0];
#pragma unroll
        for (int e = 0; e < E_N; e++) {
            float c0 = Q0.x*sw20[e][0] + Q0.y*sw20[e][1];
            float c1 = Q1.x*sw21[e][0] + Q1.y*sw21[e][1] + Q1.z*sw21[e][2];
            float c2 = Q2.x*sw21[e][0] + Q2.y*sw21[e][1] + Q2.z*sw21[e][2];
            float c3 = Q3.x*sw21[e][0] + Q3.y*sw21[e][1] + Q3.z*sw21[e][2];
            reinterpret_cast<float4*>(g_coef)[(e * C_N + c) * NT + NT3 + t] =
                make_float4(c0, c1, c2, c3);
        }
    }
    if (tid < I_N) {
        int i = tid;
#pragma unroll
        for (int e = 0; e < E_N; e++) {
            reinterpret_cast<float4*>(g_coef)[(e * C_N + c) * NT + NT3 + NT2 + i] =
                make_float4(g_U1S[0][i] * sw10[e], g_U1S[1][i] * sw11[e],
                            g_U1S[2][i] * sw11[e], g_U1S[3][i] * sw11[e]);
        }
    }
}

// ---------------- kernel C: evaluation, nested Horner, 1 item/thread ------------
// block = (channel c, species e), 128 threads, thread tid -> position start+tid.
// Removes the 25% duplicate-item FFMA waste of the 2-item scheme; latency hidden
// by occupancy (regs ~55 -> 8 blocks/SM, 32 warps) instead of per-thread ILP.
__global__ void __launch_bounds__(128, 8) main_kernel(const float* __restrict__ a_i,
                                                      float* __restrict__ out) {
    __shared__ __align__(16) float4 s_coef[NT];   // 15.5 KB
    int c   = blockIdx.x;
    int e   = blockIdx.y;
    int tid = threadIdx.x;

    const float4* src = reinterpret_cast<const float4*>(
        g_coef + (e * C_N + c) * NT * NCOMP);
#pragma unroll 4
    for (int i = tid; i < NT; i += 128) s_coef[i] = src[i];
    __syncthreads();

    int start = g_segstart[e], end = g_segstart[e + 1];

    for (int pos = start + tid; pos < end; pos += 128) {
        int b = g_perm[pos];

        float x[16];
        {
            const float4* xp = reinterpret_cast<const float4*>(a_i + (b * C_N + c) * I_N);
            float4 v0 = xp[0], v1 = xp[1], v2 = xp[2], v3 = xp[3];
            x[0]=v0.x;  x[1]=v0.y;  x[2]=v0.z;  x[3]=v0.w;
            x[4]=v1.x;  x[5]=v1.y;  x[6]=v1.z;  x[7]=v1.w;
            x[8]=v2.x;  x[9]=v2.y;  x[10]=v2.z; x[11]=v2.w;
            x[12]=v3.x; x[13]=v3.y; x[14]=v3.z; x[15]=v3.w;
        }

        float o0 = 0.f, o1 = 0.f, o2 = 0.f, o3 = 0.f;
        int t = 0, tp = 0;
#pragma unroll
        for (int a = 0; a < I_N; a++) {
            float t20, t21, t22, t23;
            float4 cl = s_coef[NT3 + NT2 + a];   // linear coef A1_a
#pragma unroll
            for (int b2 = a; b2 < I_N; b2++) {
                float4 cq = s_coef[NT3 + tp]; tp++;
                float t30, t31, t32, t33;
                {
                    float4 cf = s_coef[t]; t++;   // c3 == b2 term absorbs A2_ab
                    t30 = fmaf(cf.x, x[b2], cq.x);
                    t31 = fmaf(cf.y, x[b2], cq.y);
                    t32 = fmaf(cf.z, x[b2], cq.z);
                    t33 = fmaf(cf.w, x[b2], cq.w);
                }
#pragma unroll
                for (int c3 = b2 + 1; c3 < I_N; c3++) {
                    float4 cf = s_coef[t]; t++;
                    t30 = fmaf(cf.x, x[c3], t30);
                    t31 = fmaf(cf.y, x[c3], t31);
                    t32 = fmaf(cf.z, x[c3], t32);
                    t33 = fmaf(cf.w, x[c3], t33);
                }
                if (b2 == a) {   // first b-fold absorbs A1_a
                    t20 = fmaf(t30, x[b2], cl.x);
                    t21 = fmaf(t31, x[b2], cl.y);
                    t22 = fmaf(t32, x[b2], cl.z);
                    t23 = fmaf(t33, x[b2], cl.w);
                } else {
                    t20 = fmaf(t30, x[b2], t20);
                    t21 = fmaf(t31, x[b2], t21);
                    t22 = fmaf(t32, x[b2], t22);
                    t23 = fmaf(t33, x[b2], t23);
                }
            }
            o0 = fmaf(t20, x[a], o0);
            o1 = fmaf(t21, x[a], o1);
            o2 = fmaf(t22, x[a], o2);
            o3 = fmaf(t23, x[a], o3);
        }

        // output layout: [b, 512] = concat(out0[b, c], out1[b, c*3+m])
        float* ob = out + b * 512;
        ob[c]               = o0;
        ob[128 + c * 3 + 0] = o1;
        ob[128 + c * 3 + 1] = o2;
        ob[128 + c * 3 + 2] = o3;
    }
}

// ---------------- launch --------------------------------------------------------
extern "C" void kernel_launch(void* const* d_in, const int* in_sizes, int n_in,
                              void* d_out, int out_size) {
    const float* a_i   = (const float*)d_in[0];
    const float* na    = (const float*)d_in[1];
    const float* U3_l0 = (const float*)d_in[2];
    const float* U2_l0 = (const float*)d_in[3];
    const float* U1_l0 = (const float*)d_in[4];
    const float* W3_l0 = (const float*)d_in[5];
    const float* W2_l0 = (const float*)d_in[6];
    const float* W1_l0 = (const float*)d_in[7];
    const float* U3_l1 = (const float*)d_in[8];
    const float* U2_l1 = (const float*)d_in[9];
    const float* U1_l1 = (const float*)d_in[10];
    const float* W3_l1 = (const float*)d_in[11];
    const float* W2_l1 = (const float*)d_in[12];
    const float* W1_l1 = (const float*)d_in[13];
    float* out = (float*)d_out;

    prep_kernel<<<33, 1024>>>(na, U3_l0, U3_l1, U2_l0, U2_l1, U1_l0, U1_l1);
    coef_kernel<<<C_N, 512>>>(W3_l0, W2_l0, W1_l0, W3_l1, W2_l1, W1_l1);
    dim3 grid(C_N, E_N);
    main_kernel<<<grid, 128>>>(a_i, out);
}

// round 11
// speedup vs baseline: 5.8949x; 1.0382x over previous
#include <cuda_runtime.h>

#define B_N   1024
#define C_N   128
#define I_N   16
#define E_N   10
#define NT3   816           // cubic monomials i0<=i1<=i2
#define NT2   136           // quadratic monomials
#define NT    968           // 816 + 136 + 16
#define NCOMP 4             // L=0 scalar + 3 components of L=1

// ---------------- device scratch (static globals; no allocation) ----------------
__device__ int   g_perm[B_N];
__device__ int   g_sortspec[B_N];     // species of g_perm[pos]
__device__ __align__(32) float g_U3S[NCOMP][NT3][8];
__device__ __align__(16) float g_U2S[NCOMP][NT2][4];
__device__ float g_U1S[NCOMP][I_N];
// coefficient table: [c][e][t][comp] -> per-c slab contiguous 154.9 KB
__device__ __align__(16) float g_coef[C_N * E_N * NT * NCOMP];  // 19.8 MB

// ---------------- kernel A: sort (block 0) + U symmetrization (blocks 1..32) ---
__global__ void prep_kernel(const float* __restrict__ node_attrs,
                            const float* __restrict__ U3_l0,
                            const float* __restrict__ U3_l1,
                            const float* __restrict__ U2_l0,
                            const float* __restrict__ U2_l1,
                            const float* __restrict__ U1_l0,
                            const float* __restrict__ U1_l1) {
    int tid = threadIdx.x;   // 1024
    if (blockIdx.x == 0) {
        __shared__ int s_hist[E_N];
        __shared__ int s_off[E_N];
        if (tid < E_N) s_hist[tid] = 0;
        __syncthreads();
        const float* na = node_attrs + tid * E_N;
        int e = 0;
#pragma unroll
        for (int j = 0; j < E_N; j++) if (na[j] > 0.5f) e = j;
        atomicAdd(&s_hist[e], 1);
        __syncthreads();
        if (tid == 0) {
            int acc = 0;
            for (int j = 0; j < E_N; j++) { s_off[j] = acc; acc += s_hist[j]; }
        }
        __syncthreads();
        int pos = atomicAdd(&s_off[e], 1);
        g_perm[pos] = tid;
        g_sortspec[pos] = e;
        return;
    }

    int gtid = (blockIdx.x - 1) * blockDim.x + tid;   // 0..32767

    if (gtid < NCOMP * NT3 * 8) {
        int k    = gtid & 7;
        int t    = (gtid >> 3) % NT3;
        int comp = gtid / (NT3 * 8);
        int rem = t, a = 0;
        for (int ap = 0; ap < I_N; ap++) {
            int sz = (I_N - ap) * (I_N - ap + 1) / 2;
            if (rem < sz) { a = ap; break; }
            rem -= sz;
        }
        int b = a;
        for (int bp = a; bp < I_N; bp++) {
            int sz = I_N - bp;
            if (rem < sz) { b = bp; break; }
            rem -= sz;
        }
        int c = b + rem;
        float inv = (a == c) ? (1.f / 6.f) : ((a == b || b == c) ? 0.5f : 1.f);
        int kN; const float* U;
        if (comp == 0) { kN = 5; U = U3_l0; }
        else           { kN = 7; U = U3_l1 + (comp - 1) * (I_N * I_N * I_N * 7); }
        float s = 0.f;
        if (k < kN) {
            auto at = [&](int i0, int i1, int i2) {
                return U[((i0 * I_N + i1) * I_N + i2) * kN + k];
            };
            s = at(a,b,c) + at(a,c,b) + at(b,a,c) + at(b,c,a) + at(c,a,b) + at(c,b,a);
            s *= inv;
        }
        g_U3S[comp][t][k] = s;
    }
    if (gtid < NCOMP * NT2 * 4) {
        int k    = gtid & 3;
        int t    = (gtid >> 2) % NT2;
        int comp = gtid / (NT2 * 4);
        int rem = t, a = 0;
        for (int ap = 0; ap < I_N; ap++) {
            int sz = I_N - ap;
            if (rem < sz) { a = ap; break; }
            rem -= sz;
        }
        int b = a + rem;
        int kN; const float* U;
        if (comp == 0) { kN = 2; U = U2_l0; }
        else           { kN = 3; U = U2_l1 + (comp - 1) * (I_N * I_N * 3); }
        float s = 0.f;
        if (k < kN) {
            s = U[(a * I_N + b) * kN + k];
            if (a != b) s += U[(b * I_N + a) * kN + k];
        }
        g_U2S[comp][t][k] = s;
    }
    if (gtid < NCOMP * I_N) {
        int comp = gtid / I_N, i = gtid % I_N;
        g_U1S[comp][i] = (comp == 0) ? U1_l0[i] : U1_l1[(comp - 1) * I_N + i];
    }
}

// ---------------- kernel B: coefficient fold, one block per channel -------------
// Writes [c][e][t][comp] so the eval kernel's per-c slab is contiguous.
__global__ void __launch_bounds__(512) coef_kernel(const float* __restrict__ W3_l0,
                                                   const float* __restrict__ W2_l0,
                                                   const float* __restrict__ W1_l0,
                                                   const float* __restrict__ W3_l1,
                                                   const float* __restrict__ W2_l1,
                                                   const float* __restrict__ W1_l1) {
    int c   = blockIdx.x;
    int tid = threadIdx.x;   // 512
    __shared__ float sw30[E_N][5], sw31[E_N][7];
    __shared__ float sw20[E_N][2], sw21[E_N][3];
    __shared__ float sw10[E_N], sw11[E_N];
    if (tid < E_N * 5) sw30[tid / 5][tid % 5] = W3_l0[tid * C_N + c];
    if (tid < E_N * 7) sw31[tid / 7][tid % 7] = W3_l1[tid * C_N + c];
    if (tid < E_N * 2) sw20[tid / 2][tid % 2] = W2_l0[tid * C_N + c];
    if (tid < E_N * 3) sw21[tid / 3][tid % 3] = W2_l1[tid * C_N + c];
    if (tid < E_N) { sw10[tid] = W1_l0[tid * C_N + c]; sw11[tid] = W1_l1[tid * C_N + c]; }
    __syncthreads();

    for (int t = tid; t < NT3; t += 512) {
        float4 A0 = reinterpret_cast<const float4*>(&g_U3S[0][t][0])[0];
        float4 A1 = reinterpret_cast<const float4*>(&g_U3S[0][t][0])[1];
        float4 B0 = reinterpret_cast<const float4*>(&g_U3S[1][t][0])[0];
        float4 B1 = reinterpret_cast<const float4*>(&g_U3S[1][t][0])[1];
        float4 C0 = reinterpret_cast<const float4*>(&g_U3S[2][t][0])[0];
        float4 C1 = reinterpret_cast<const float4*>(&g_U3S[2][t][0])[1];
        float4 D0 = reinterpret_cast<const float4*>(&g_U3S[3][t][0])[0];
        float4 D1 = reinterpret_cast<const float4*>(&g_U3S[3][t][0])[1];
#pragma unroll
        for (int e = 0; e < E_N; e++) {
            float c0 = A0.x*sw30[e][0] + A0.y*sw30[e][1] + A0.z*sw30[e][2]
                     + A0.w*sw30[e][3] + A1.x*sw30[e][4];
            float c1 = B0.x*sw31[e][0] + B0.y*sw31[e][1] + B0.z*sw31[e][2]
                     + B0.w*sw31[e][3] + B1.x*sw31[e][4] + B1.y*sw31[e][5] + B1.z*sw31[e][6];
            float c2 = C0.x*sw31[e][0] + C0.y*sw31[e][1] + C0.z*sw31[e][2]
                     + C0.w*sw31[e][3] + C1.x*sw31[e][4] + C1.y*sw31[e][5] + C1.z*sw31[e][6];
            float c3 = D0.x*sw31[e][0] + D0.y*sw31[e][1] + D0.z*sw31[e][2]
                     + D0.w*sw31[e][3] + D1.x*sw31[e][4] + D1.y*sw31[e][5] + D1.z*sw31[e][6];
            reinterpret_cast<float4*>(g_coef)[(c * E_N + e) * NT + t] =
                make_float4(c0, c1, c2, c3);
        }
    }
    for (int t = tid; t < NT2; t += 512) {
        float4 Q0 = reinterpret_cast<const float4*>(&g_U2S[0][t][0])[0];
        float4 Q1 = reinterpret_cast<const float4*>(&g_U2S[1][t][0])[0];
        float4 Q2 = reinterpret_cast<const float4*>(&g_U2S[2][t][0])[0];
        float4 Q3 = reinterpret_cast<const float4*>(&g_U2S[3][t][0])[0];
#pragma unroll
        for (int e = 0; e < E_N; e++) {
            float c0 = Q0.x*sw20[e][0] + Q0.y*sw20[e][1];
            float c1 = Q1.x*sw21[e][0] + Q1.y*sw21[e][1] + Q1.z*sw21[e][2];
            float c2 = Q2.x*sw21[e][0] + Q2.y*sw21[e][1] + Q2.z*sw21[e][2];
            float c3 = Q3.x*sw21[e][0] + Q3.y*sw21[e][1] + Q3.z*sw21[e][2];
            reinterpret_cast<float4*>(g_coef)[(c * E_N + e) * NT + NT3 + t] =
                make_float4(c0, c1, c2, c3);
        }
    }
    if (tid < I_N) {
        int i = tid;
#pragma unroll
        for (int e = 0; e < E_N; e++) {
            reinterpret_cast<float4*>(g_coef)[(c * E_N + e) * NT + NT3 + NT2 + i] =
                make_float4(g_U1S[0][i] * sw10[e], g_U1S[1][i] * sw11[e],
                            g_U1S[2][i] * sw11[e], g_U1S[3][i] * sw11[e]);
        }
    }
}

// ---------------- kernel C: evaluation, nested Horner, block = channel ----------
// 1024 threads = 1024 batch items (zero padding waste), all 10 species' slabs
// in 154.9 KB dynamic SMEM (1 block/SM, 32 warps). Batch species-sorted, so
// coefficient LDS are warp-broadcasts except ~9 boundary warps (2-way).
__global__ void __launch_bounds__(1024, 1) main_kernel(const float* __restrict__ a_i,
                                                       float* __restrict__ out) {
    extern __shared__ __align__(16) float4 s_coef[];   // [E_N * NT]
    int c   = blockIdx.x;
    int tid = threadIdx.x;

    const float4* src = reinterpret_cast<const float4*>(g_coef + c * E_N * NT * NCOMP);
#pragma unroll 2
    for (int i = tid; i < E_N * NT; i += 1024) s_coef[i] = src[i];
    __syncthreads();

    int b = g_perm[tid];
    int e = g_sortspec[tid];
    const float4* base = s_coef + e * NT;

    float x[16];
    {
        const float4* xp = reinterpret_cast<const float4*>(a_i + (b * C_N + c) * I_N);
        float4 v0 = xp[0], v1 = xp[1], v2 = xp[2], v3 = xp[3];
        x[0]=v0.x;  x[1]=v0.y;  x[2]=v0.z;  x[3]=v0.w;
        x[4]=v1.x;  x[5]=v1.y;  x[6]=v1.z;  x[7]=v1.w;
        x[8]=v2.x;  x[9]=v2.y;  x[10]=v2.z; x[11]=v2.w;
        x[12]=v3.x; x[13]=v3.y; x[14]=v3.z; x[15]=v3.w;
    }

    float o0 = 0.f, o1 = 0.f, o2 = 0.f, o3 = 0.f;
    int t = 0, tp = 0;
#pragma unroll
    for (int a = 0; a < I_N; a++) {
        float t20, t21, t22, t23;
        float4 cl = base[NT3 + NT2 + a];   // linear coef A1_a
#pragma unroll
        for (int b2 = a; b2 < I_N; b2++) {
            float4 cq = base[NT3 + tp]; tp++;
            float t30, t31, t32, t33;
            {
                float4 cf = base[t]; t++;   // c3 == b2 term absorbs A2_ab
                t30 = fmaf(cf.x, x[b2], cq.x);
                t31 = fmaf(cf.y, x[b2], cq.y);
                t32 = fmaf(cf.z, x[b2], cq.z);
                t33 = fmaf(cf.w, x[b2], cq.w);
            }
#pragma unroll
            for (int c3 = b2 + 1; c3 < I_N; c3++) {
                float4 cf = base[t]; t++;
                t30 = fmaf(cf.x, x[c3], t30);
                t31 = fmaf(cf.y, x[c3], t31);
                t32 = fmaf(cf.z, x[c3], t32);
                t33 = fmaf(cf.w, x[c3], t33);
            }
            if (b2 == a) {   // first b-fold absorbs A1_a
                t20 = fmaf(t30, x[b2], cl.x);
                t21 = fmaf(t31, x[b2], cl.y);
                t22 = fmaf(t32, x[b2], cl.z);
                t23 = fmaf(t33, x[b2], cl.w);
            } else {
                t20 = fmaf(t30, x[b2], t20);
                t21 = fmaf(t31, x[b2], t21);
                t22 = fmaf(t32, x[b2], t22);
                t23 = fmaf(t33, x[b2], t23);
            }
        }
        o0 = fmaf(t20, x[a], o0);
        o1 = fmaf(t21, x[a], o1);
        o2 = fmaf(t22, x[a], o2);
        o3 = fmaf(t23, x[a], o3);
    }

    // output layout: [b, 512] = concat(out0[b, c], out1[b, c*3+m])
    float* ob = out + b * 512;
    ob[c]               = o0;
    ob[128 + c * 3 + 0] = o1;
    ob[128 + c * 3 + 1] = o2;
    ob[128 + c * 3 + 2] = o3;
}

// ---------------- launch --------------------------------------------------------
extern "C" void kernel_launch(void* const* d_in, const int* in_sizes, int n_in,
                              void* d_out, int out_size) {
    const float* a_i   = (const float*)d_in[0];
    const float* na    = (const float*)d_in[1];
    const float* U3_l0 = (const float*)d_in[2];
    const float* U2_l0 = (const float*)d_in[3];
    const float* U1_l0 = (const float*)d_in[4];
    const float* W3_l0 = (const float*)d_in[5];
    const float* W2_l0 = (const float*)d_in[6];
    const float* W1_l0 = (const float*)d_in[7];
    const float* U3_l1 = (const float*)d_in[8];
    const float* U2_l1 = (const float*)d_in[9];
    const float* U1_l1 = (const float*)d_in[10];
    const float* W3_l1 = (const float*)d_in[11];
    const float* W2_l1 = (const float*)d_in[12];
    const float* W1_l1 = (const float*)d_in[13];
    float* out = (float*)d_out;

    const int smem_bytes = E_N * NT * (int)sizeof(float4);  // 154880
    cudaFuncSetAttribute(main_kernel, cudaFuncAttributeMaxDynamicSharedMemorySize,
                         smem_bytes);

    prep_kernel<<<33, 1024>>>(na, U3_l0, U3_l1, U2_l0, U2_l1, U1_l0, U1_l1);
    coef_kernel<<<C_N, 512>>>(W3_l0, W2_l0, W1_l0, W3_l1, W2_l1, W1_l1);
    main_kernel<<<C_N, 1024, smem_bytes>>>(a_i, out);
}

// round 12
// speedup vs baseline: 6.4494x; 1.0941x over previous
#include <cuda_runtime.h>

#define B_N   1024
#define C_N   128
#define I_N   16
#define E_N   10
#define NT3   816           // cubic monomials i0<=i1<=i2
#define NT2   136           // quadratic monomials
#define NT    968           // 816 + 136 + 16
#define NCOMP 4             // L=0 scalar + 3 components of L=1

// ---------------- device scratch (static globals; no allocation) ----------------
__device__ int   g_perm[B_N];
__device__ int   g_sortspec[B_N];     // species of g_perm[pos]
__device__ __align__(32) float g_U3S[NCOMP][NT3][8];
__device__ __align__(16) float g_U2S[NCOMP][NT2][4];
__device__ float g_U1S[NCOMP][I_N];

// ---------------- kernel A: sort (block 0) + U symmetrization (blocks 1..32) ---
__global__ void prep_kernel(const float* __restrict__ node_attrs,
                            const float* __restrict__ U3_l0,
                            const float* __restrict__ U3_l1,
                            const float* __restrict__ U2_l0,
                            const float* __restrict__ U2_l1,
                            const float* __restrict__ U1_l0,
                            const float* __restrict__ U1_l1) {
    int tid = threadIdx.x;   // 1024
    if (blockIdx.x == 0) {
        __shared__ int s_hist[E_N];
        __shared__ int s_off[E_N];
        if (tid < E_N) s_hist[tid] = 0;
        __syncthreads();
        const float* na = node_attrs + tid * E_N;
        int e = 0;
#pragma unroll
        for (int j = 0; j < E_N; j++) if (na[j] > 0.5f) e = j;
        atomicAdd(&s_hist[e], 1);
        __syncthreads();
        if (tid == 0) {
            int acc = 0;
            for (int j = 0; j < E_N; j++) { s_off[j] = acc; acc += s_hist[j]; }
        }
        __syncthreads();
        int pos = atomicAdd(&s_off[e], 1);
        g_perm[pos] = tid;
        g_sortspec[pos] = e;
        return;
    }

    int gtid = (blockIdx.x - 1) * blockDim.x + tid;   // 0..32767

    if (gtid < NCOMP * NT3 * 8) {
        int k    = gtid & 7;
        int t    = (gtid >> 3) % NT3;
        int comp = gtid / (NT3 * 8);
        int rem = t, a = 0;
        for (int ap = 0; ap < I_N; ap++) {
            int sz = (I_N - ap) * (I_N - ap + 1) / 2;
            if (rem < sz) { a = ap; break; }
            rem -= sz;
        }
        int b = a;
        for (int bp = a; bp < I_N; bp++) {
            int sz = I_N - bp;
            if (rem < sz) { b = bp; break; }
            rem -= sz;
        }
        int c = b + rem;
        float inv = (a == c) ? (1.f / 6.f) : ((a == b || b == c) ? 0.5f : 1.f);
        int kN; const float* U;
        if (comp == 0) { kN = 5; U = U3_l0; }
        else           { kN = 7; U = U3_l1 + (comp - 1) * (I_N * I_N * I_N * 7); }
        float s = 0.f;
        if (k < kN) {
            auto at = [&](int i0, int i1, int i2) {
                return U[((i0 * I_N + i1) * I_N + i2) * kN + k];
            };
            s = at(a,b,c) + at(a,c,b) + at(b,a,c) + at(b,c,a) + at(c,a,b) + at(c,b,a);
            s *= inv;
        }
        g_U3S[comp][t][k] = s;
    }
    if (gtid < NCOMP * NT2 * 4) {
        int k    = gtid & 3;
        int t    = (gtid >> 2) % NT2;
        int comp = gtid / (NT2 * 4);
        int rem = t, a = 0;
        for (int ap = 0; ap < I_N; ap++) {
            int sz = I_N - ap;
            if (rem < sz) { a = ap; break; }
            rem -= sz;
        }
        int b = a + rem;
        int kN; const float* U;
        if (comp == 0) { kN = 2; U = U2_l0; }
        else           { kN = 3; U = U2_l1 + (comp - 1) * (I_N * I_N * 3); }
        float s = 0.f;
        if (k < kN) {
            s = U[(a * I_N + b) * kN + k];
            if (a != b) s += U[(b * I_N + a) * kN + k];
        }
        g_U2S[comp][t][k] = s;
    }
    if (gtid < NCOMP * I_N) {
        int comp = gtid / I_N, i = gtid % I_N;
        g_U1S[comp][i] = (comp == 0) ? U1_l0[i] : U1_l1[(comp - 1) * I_N + i];
    }
}

// ---------------- kernel B: fused fold + evaluation, block = channel ------------
// Prologue: fold W into all 10 species' coefficient slabs directly into SMEM
// (reads L2-resident g_U3S once per block = 128x total; no DRAM round-trip).
// Eval: 1024 threads = 1024 sorted batch items, zero padding waste; nested
// Horner; coefficient LDS are warp-broadcasts except ~9 boundary warps.
__global__ void __launch_bounds__(1024, 1) main_kernel(const float* __restrict__ a_i,
                                                       const float* __restrict__ W3_l0,
                                                       const float* __restrict__ W2_l0,
                                                       const float* __restrict__ W1_l0,
                                                       const float* __restrict__ W3_l1,
                                                       const float* __restrict__ W2_l1,
                                                       const float* __restrict__ W1_l1,
                                                       float* __restrict__ out) {
    extern __shared__ __align__(16) float4 s_coef[];   // [E_N * NT] = 154.9 KB
    __shared__ float sw30[E_N][5], sw31[E_N][7];
    __shared__ float sw20[E_N][2], sw21[E_N][3];
    __shared__ float sw10[E_N], sw11[E_N];
    int c   = blockIdx.x;
    int tid = threadIdx.x;

    // ---- stage per-channel species weights ----------------------------------
    if (tid < E_N * 5) sw30[tid / 5][tid % 5] = W3_l0[tid * C_N + c];
    if (tid < E_N * 7) sw31[tid / 7][tid % 7] = W3_l1[tid * C_N + c];
    if (tid < E_N * 2) sw20[tid / 2][tid % 2] = W2_l0[tid * C_N + c];
    if (tid < E_N * 3) sw21[tid / 3][tid % 3] = W2_l1[tid * C_N + c];
    if (tid < E_N) { sw10[tid] = W1_l0[tid * C_N + c]; sw11[tid] = W1_l1[tid * C_N + c]; }
    __syncthreads();

    // ---- fold: coefficients for all species, straight into SMEM -------------
    for (int t = tid; t < NT3; t += 1024) {
        float4 A0 = reinterpret_cast<const float4*>(&g_U3S[0][t][0])[0];
        float4 A1 = reinterpret_cast<const float4*>(&g_U3S[0][t][0])[1];
        float4 B0 = reinterpret_cast<const float4*>(&g_U3S[1][t][0])[0];
        float4 B1 = reinterpret_cast<const float4*>(&g_U3S[1][t][0])[1];
        float4 C0 = reinterpret_cast<const float4*>(&g_U3S[2][t][0])[0];
        float4 C1 = reinterpret_cast<const float4*>(&g_U3S[2][t][0])[1];
        float4 D0 = reinterpret_cast<const float4*>(&g_U3S[3][t][0])[0];
        float4 D1 = reinterpret_cast<const float4*>(&g_U3S[3][t][0])[1];
#pragma unroll
        for (int e = 0; e < E_N; e++) {
            float c0 = A0.x*sw30[e][0] + A0.y*sw30[e][1] + A0.z*sw30[e][2]
                     + A0.w*sw30[e][3] + A1.x*sw30[e][4];
            float c1 = B0.x*sw31[e][0] + B0.y*sw31[e][1] + B0.z*sw31[e][2]
                     + B0.w*sw31[e][3] + B1.x*sw31[e][4] + B1.y*sw31[e][5] + B1.z*sw31[e][6];
            float c2 = C0.x*sw31[e][0] + C0.y*sw31[e][1] + C0.z*sw31[e][2]
                     + C0.w*sw31[e][3] + C1.x*sw31[e][4] + C1.y*sw31[e][5] + C1.z*sw31[e][6];
            float c3 = D0.x*sw31[e][0] + D0.y*sw31[e][1] + D0.z*sw31[e][2]
                     + D0.w*sw31[e][3] + D1.x*sw31[e][4] + D1.y*sw31[e][5] + D1.z*sw31[e][6];
            s_coef[e * NT + t] = make_float4(c0, c1, c2, c3);
        }
    }
    for (int t = tid; t < NT2; t += 1024) {
        float4 Q0 = reinterpret_cast<const float4*>(&g_U2S[0][t][0])[0];
        float4 Q1 = reinterpret_cast<const float4*>(&g_U2S[1][t][0])[0];
        float4 Q2 = reinterpret_cast<const float4*>(&g_U2S[2][t][0])[0];
        float4 Q3 = reinterpret_cast<const float4*>(&g_U2S[3][t][0])[0];
#pragma unroll
        for (int e = 0; e < E_N; e++) {
            float c0 = Q0.x*sw20[e][0] + Q0.y*sw20[e][1];
            float c1 = Q1.x*sw21[e][0] + Q1.y*sw21[e][1] + Q1.z*sw21[e][2];
            float c2 = Q2.x*sw21[e][0] + Q2.y*sw21[e][1] + Q2.z*sw21[e][2];
            float c3 = Q3.x*sw21[e][0] + Q3.y*sw21[e][1] + Q3.z*sw21[e][2];
            s_coef[e * NT + NT3 + t] = make_float4(c0, c1, c2, c3);
        }
    }
    if (tid < I_N) {
        int i = tid;
#pragma unroll
        for (int e = 0; e < E_N; e++) {
            s_coef[e * NT + NT3 + NT2 + i] =
                make_float4(g_U1S[0][i] * sw10[e], g_U1S[1][i] * sw11[e],
                            g_U1S[2][i] * sw11[e], g_U1S[3][i] * sw11[e]);
        }
    }
    __syncthreads();

    // ---- eval ----------------------------------------------------------------
    int b = g_perm[tid];
    int e = g_sortspec[tid];
    const float4* base = s_coef + e * NT;

    float x[16];
    {
        const float4* xp = reinterpret_cast<const float4*>(a_i + (b * C_N + c) * I_N);
        float4 v0 = xp[0], v1 = xp[1], v2 = xp[2], v3 = xp[3];
        x[0]=v0.x;  x[1]=v0.y;  x[2]=v0.z;  x[3]=v0.w;
        x[4]=v1.x;  x[5]=v1.y;  x[6]=v1.z;  x[7]=v1.w;
        x[8]=v2.x;  x[9]=v2.y;  x[10]=v2.z; x[11]=v2.w;
        x[12]=v3.x; x[13]=v3.y; x[14]=v3.z; x[15]=v3.w;
    }

    float o0 = 0.f, o1 = 0.f, o2 = 0.f, o3 = 0.f;
    int t = 0, tp = 0;
#pragma unroll
    for (int a = 0; a < I_N; a++) {
        float t20, t21, t22, t23;
        float4 cl = base[NT3 + NT2 + a];   // linear coef A1_a
#pragma unroll
        for (int b2 = a; b2 < I_N; b2++) {
            float4 cq = base[NT3 + tp]; tp++;
            float t30, t31, t32, t33;
            {
                float4 cf = base[t]; t++;   // c3 == b2 term absorbs A2_ab
                t30 = fmaf(cf.x, x[b2], cq.x);
                t31 = fmaf(cf.y, x[b2], cq.y);
                t32 = fmaf(cf.z, x[b2], cq.z);
                t33 = fmaf(cf.w, x[b2], cq.w);
            }
#pragma unroll
            for (int c3 = b2 + 1; c3 < I_N; c3++) {
                float4 cf = base[t]; t++;
                t30 = fmaf(cf.x, x[c3], t30);
                t31 = fmaf(cf.y, x[c3], t31);
                t32 = fmaf(cf.z, x[c3], t32);
                t33 = fmaf(cf.w, x[c3], t33);
            }
            if (b2 == a) {   // first b-fold absorbs A1_a
                t20 = fmaf(t30, x[b2], cl.x);
                t21 = fmaf(t31, x[b2], cl.y);
                t22 = fmaf(t32, x[b2], cl.z);
                t23 = fmaf(t33, x[b2], cl.w);
            } else {
                t20 = fmaf(t30, x[b2], t20);
                t21 = fmaf(t31, x[b2], t21);
                t22 = fmaf(t32, x[b2], t22);
                t23 = fmaf(t33, x[b2], t23);
            }
        }
        o0 = fmaf(t20, x[a], o0);
        o1 = fmaf(t21, x[a], o1);
        o2 = fmaf(t22, x[a], o2);
        o3 = fmaf(t23, x[a], o3);
    }

    // output layout: [b, 512] = concat(out0[b, c], out1[b, c*3+m])
    float* ob = out + b * 512;
    ob[c]               = o0;
    ob[128 + c * 3 + 0] = o1;
    ob[128 + c * 3 + 1] = o2;
    ob[128 + c * 3 + 2] = o3;
}

// ---------------- launch --------------------------------------------------------
extern "C" void kernel_launch(void* const* d_in, const int* in_sizes, int n_in,
                              void* d_out, int out_size) {
    const float* a_i   = (const float*)d_in[0];
    const float* na    = (const float*)d_in[1];
    const float* U3_l0 = (const float*)d_in[2];
    const float* U2_l0 = (const float*)d_in[3];
    const float* U1_l0 = (const float*)d_in[4];
    const float* W3_l0 = (const float*)d_in[5];
    const float* W2_l0 = (const float*)d_in[6];
    const float* W1_l0 = (const float*)d_in[7];
    const float* U3_l1 = (const float*)d_in[8];
    const float* U2_l1 = (const float*)d_in[9];
    const float* U1_l1 = (const float*)d_in[10];
    const float* W3_l1 = (const float*)d_in[11];
    const float* W2_l1 = (const float*)d_in[12];
    const float* W1_l1 = (const float*)d_in[13];
    float* out = (float*)d_out;

    const int smem_bytes = E_N * NT * (int)sizeof(float4);  // 154880
    cudaFuncSetAttribute(main_kernel, cudaFuncAttributeMaxDynamicSharedMemorySize,
                         smem_bytes);

    prep_kernel<<<33, 1024>>>(na, U3_l0, U3_l1, U2_l0, U2_l1, U1_l0, U1_l1);
    main_kernel<<<C_N, 1024, smem_bytes>>>(a_i, W3_l0, W2_l0, W1_l0,
                                           W3_l1, W2_l1, W1_l1, out);
}